// round 2
// baseline (speedup 1.0000x reference)
#include <cuda_runtime.h>
#include <math.h>

#define BB 4
#define SS 512
#define JJ 24
#define HH 128
#define NHEAD 8
#define HSZ 16

typedef unsigned long long ull;

// ---- f32x2 packed-math helpers (sm_103a FFMA2 path, PTX-only) -------------
__device__ __forceinline__ ull pk2(float lo, float hi) {
    ull r; asm("mov.b64 %0, {%1, %2};" : "=l"(r) : "f"(lo), "f"(hi)); return r;
}
__device__ __forceinline__ float2 upk2(ull v) {
    float2 r; asm("mov.b64 {%0, %1}, %2;" : "=f"(r.x), "=f"(r.y) : "l"(v)); return r;
}
__device__ __forceinline__ void fma2(ull& d, ull a, ull b) {
    asm("fma.rn.f32x2 %0, %1, %2, %0;" : "+l"(d) : "l"(a), "l"(b));
}
__device__ __forceinline__ void mul2(ull& d, ull a) {
    asm("mul.rn.f32x2 %0, %0, %1;" : "+l"(d) : "l"(a));
}

// Scratch (device globals — no allocation allowed)
__device__ float g_q[BB*NHEAD*JJ*SS*HSZ];   // (b,n,j,s,d)
__device__ float g_k[BB*NHEAD*JJ*SS*HSZ];
__device__ float g_v[BB*NHEAD*JJ*SS*HSZ];
__device__ float g_ao[BB*SS*JJ*HH];         // attention out, (b,s,j,h) h=n*16+d

// ---------------------------------------------------------------------------
// Kernel 1: QKV projection.  For each (j,b,mat): X(512x128) @ W(128x128)
// f32x2-packed dot products along h.
// grid (24, 4, 3), block 256, smem = (128*128 + 32*128)*4 = 80KB
// ---------------------------------------------------------------------------
__global__ void qkv_kernel(const float* __restrict__ x,
                           const float* __restrict__ qm,
                           const float* __restrict__ km,
                           const float* __restrict__ vm) {
    const int j = blockIdx.x;
    const int b = blockIdx.y;
    const int m = blockIdx.z;
    const float* W = (m == 0) ? qm : ((m == 1) ? km : vm);
    float* dst = (m == 0) ? g_q : ((m == 1) ? g_k : g_v);

    extern __shared__ float sm1[];
    float* sW = sm1;            // [128][128]  sW[h*128 + nd]
    float* sX = sm1 + HH * HH;  // [32][128]

    const int tid = threadIdx.x;

    for (int idx = tid; idx < HH * HH; idx += 256) {
        int h  = idx >> 7;
        int nd = idx & 127;
        int n  = nd >> 4;
        int d  = nd & 15;
        sW[idx] = W[((n * JJ + j) * HH + h) * HSZ + d];
    }

    const int col  = tid & 127;
    const int half = tid >> 7;
    const int n = col >> 4, d = col & 15;
    float* drow = dst + (size_t)(((b * NHEAD + n) * JJ + j) * SS) * HSZ + d;

    const int CH = 32;
    for (int s0 = 0; s0 < SS; s0 += CH) {
        __syncthreads();
        for (int idx = tid * 4; idx < CH * HH; idx += 256 * 4) {
            int r = idx >> 7;
            int h = idx & 127;
            *(float4*)&sX[idx] =
                *(const float4*)&x[(size_t)((b * SS + s0 + r) * JJ + j) * HH + h];
        }
        __syncthreads();

        ull acc2[CH / 2];
        #pragma unroll
        for (int i = 0; i < CH / 2; i++) acc2[i] = 0ull;

        for (int h = 0; h < HH; h += 4) {
            const ull w01 = pk2(sW[(h + 0) * HH + col], sW[(h + 1) * HH + col]);
            const ull w23 = pk2(sW[(h + 2) * HH + col], sW[(h + 3) * HH + col]);
            #pragma unroll
            for (int i = 0; i < CH / 2; i++) {
                const longlong2 xv = *(const longlong2*)&sX[(2 * i + half) * HH + h];
                fma2(acc2[i], (ull)xv.x, w01);
                fma2(acc2[i], (ull)xv.y, w23);
            }
        }
        #pragma unroll
        for (int i = 0; i < CH / 2; i++) {
            const float2 a = upk2(acc2[i]);
            drow[(size_t)(s0 + 2 * i + half) * HSZ] = a.x + a.y;
        }
    }
}

// ---------------------------------------------------------------------------
// Kernel 2: fused causal attention per (b,n,j). One thread per query s,
// tiled (T=16) online softmax, f32x2 packed dot products, K/V in SMEM.
// grid (24, 8, 4), block 512, smem = 512*16*2*4 = 64KB
// ---------------------------------------------------------------------------
__global__ void __launch_bounds__(512) attn_kernel() {
    const int j = blockIdx.x;
    const int n = blockIdx.y;
    const int b = blockIdx.z;

    extern __shared__ float sm2[];
    float* sK = sm2;             // [512][16]
    float* sV = sm2 + SS * HSZ;  // [512][16]

    const int tid = threadIdx.x;  // 512
    const size_t base = (size_t)(((b * NHEAD + n) * JJ + j) * SS) * HSZ;

    for (int idx = tid * 4; idx < SS * HSZ; idx += 512 * 4) {
        *(float4*)&sK[idx] = *(const float4*)&g_k[base + idx];
        *(float4*)&sV[idx] = *(const float4*)&g_v[base + idx];
    }
    __syncthreads();

    const int s = tid;

    // q as 8 packed f32x2 pairs
    ull q2[8];
    {
        const longlong2* qp = (const longlong2*)&g_q[base + (size_t)s * HSZ];
        const longlong2 a = qp[0], bq = qp[1], c = qp[2], dq = qp[3];
        q2[0] = (ull)a.x;  q2[1] = (ull)a.y;
        q2[2] = (ull)bq.x; q2[3] = (ull)bq.y;
        q2[4] = (ull)c.x;  q2[5] = (ull)c.y;
        q2[6] = (ull)dq.x; q2[7] = (ull)dq.y;
    }

    float m = -1e30f, l = 0.f;
    ull acc2[8];
    #pragma unroll
    for (int i = 0; i < 8; i++) acc2[i] = 0ull;

    const int tmax = s | 15;
    for (int t0 = 0; t0 <= tmax; t0 += 16) {
        float sc[16];
        #pragma unroll
        for (int u = 0; u < 16; u++) {
            const int t = t0 + u;
            const longlong2* kp = (const longlong2*)&sK[t * HSZ];
            const longlong2 k0 = kp[0], k1 = kp[1], k2 = kp[2], k3 = kp[3];
            ull d2 = 0ull;
            fma2(d2, q2[0], (ull)k0.x); fma2(d2, q2[1], (ull)k0.y);
            fma2(d2, q2[2], (ull)k1.x); fma2(d2, q2[3], (ull)k1.y);
            fma2(d2, q2[4], (ull)k2.x); fma2(d2, q2[5], (ull)k2.y);
            fma2(d2, q2[6], (ull)k3.x); fma2(d2, q2[7], (ull)k3.y);
            const float2 dd = upk2(d2);
            const float v = (dd.x + dd.y) * 0.25f;  // 1/sqrt(16)
            sc[u] = (t <= s) ? v : -1e30f;
        }

        // tile max (tree)
        float t0m = fmaxf(sc[0], sc[1]),  t1m = fmaxf(sc[2], sc[3]);
        float t2m = fmaxf(sc[4], sc[5]),  t3m = fmaxf(sc[6], sc[7]);
        float t4m = fmaxf(sc[8], sc[9]),  t5m = fmaxf(sc[10], sc[11]);
        float t6m = fmaxf(sc[12], sc[13]), t7m = fmaxf(sc[14], sc[15]);
        t0m = fmaxf(t0m, t1m); t2m = fmaxf(t2m, t3m);
        t4m = fmaxf(t4m, t5m); t6m = fmaxf(t6m, t7m);
        const float tm = fmaxf(fmaxf(t0m, t2m), fmaxf(t4m, t6m));

        const float mnew = fmaxf(m, tm);
        const float corr = __expf(m - mnew);
        m = mnew;
        l *= corr;
        const ull c2 = pk2(corr, corr);
        #pragma unroll
        for (int i = 0; i < 8; i++) mul2(acc2[i], c2);

        #pragma unroll
        for (int u = 0; u < 16; u++) {
            const float p = __expf(sc[u] - m);
            l += p;
            const ull p2 = pk2(p, p);
            const longlong2* vp = (const longlong2*)&sV[(t0 + u) * HSZ];
            const longlong2 v0 = vp[0], v1 = vp[1], v2 = vp[2], v3 = vp[3];
            fma2(acc2[0], p2, (ull)v0.x); fma2(acc2[1], p2, (ull)v0.y);
            fma2(acc2[2], p2, (ull)v1.x); fma2(acc2[3], p2, (ull)v1.y);
            fma2(acc2[4], p2, (ull)v2.x); fma2(acc2[5], p2, (ull)v2.y);
            fma2(acc2[6], p2, (ull)v3.x); fma2(acc2[7], p2, (ull)v3.y);
        }
    }

    const float inv = 1.f / l;
    float* o = &g_ao[(size_t)((b * SS + s) * JJ + j) * HH + n * HSZ];
    #pragma unroll
    for (int i = 0; i < 4; i++) {
        const float2 a = upk2(acc2[2 * i]);
        const float2 c = upk2(acc2[2 * i + 1]);
        float4 r;
        r.x = a.x * inv; r.y = a.y * inv;
        r.z = c.x * inv; r.w = c.y * inv;
        *(float4*)&o[4 * i] = r;
    }
}

// ---------------------------------------------------------------------------
// Kernel 3: per-joint output projection, f32x2 packed.
// grid (24, 16), block 256, smem = (128*128 + 32*128)*4 = 80KB
// ---------------------------------------------------------------------------
__global__ void proj_kernel(const float* __restrict__ P, float* __restrict__ out) {
    const int j  = blockIdx.x;
    const int r0 = blockIdx.y * 128;

    extern __shared__ float sm3[];
    float* sP = sm3;            // [128][128]
    float* sA = sm3 + HH * HH;  // [32][128]

    const int tid = threadIdx.x;

    for (int idx = tid * 4; idx < HH * HH; idx += 256 * 4) {
        *(float4*)&sP[idx] = *(const float4*)&P[(size_t)j * HH * HH + idx];
    }

    const int col  = tid & 127;
    const int half = tid >> 7;

    for (int c = 0; c < 128; c += 32) {
        __syncthreads();
        for (int idx = tid * 4; idx < 32 * HH; idx += 256 * 4) {
            int r = idx >> 7;
            int h = idx & 127;
            *(float4*)&sA[idx] =
                *(const float4*)&g_ao[(size_t)((r0 + c + r) * JJ + j) * HH + h];
        }
        __syncthreads();

        ull acc2[16];
        #pragma unroll
        for (int i = 0; i < 16; i++) acc2[i] = 0ull;

        for (int h = 0; h < HH; h += 4) {
            const ull w01 = pk2(sP[(h + 0) * HH + col], sP[(h + 1) * HH + col]);
            const ull w23 = pk2(sP[(h + 2) * HH + col], sP[(h + 3) * HH + col]);
            #pragma unroll
            for (int i = 0; i < 16; i++) {
                const longlong2 a = *(const longlong2*)&sA[(2 * i + half) * HH + h];
                fma2(acc2[i], (ull)a.x, w01);
                fma2(acc2[i], (ull)a.y, w23);
            }
        }
        #pragma unroll
        for (int i = 0; i < 16; i++) {
            const float2 a = upk2(acc2[i]);
            out[(size_t)((r0 + c + 2 * i + half) * JJ + j) * HH + col] = a.x + a.y;
        }
    }
}

// ---------------------------------------------------------------------------
// Kernel 4: residual + LayerNorm, in place on d_out. One warp per row.
// ---------------------------------------------------------------------------
__global__ void ln_kernel(const float* __restrict__ x,
                          const float* __restrict__ gamma,
                          const float* __restrict__ beta,
                          float* __restrict__ out) {
    const int row  = blockIdx.x * 8 + (threadIdx.x >> 5);
    const int lane = threadIdx.x & 31;
    const size_t off = (size_t)row * HH + lane * 4;

    const float4 o  = *(const float4*)(out + off);
    const float4 xr = *(const float4*)(x + off);
    const float v0 = o.x + xr.x, v1 = o.y + xr.y, v2 = o.z + xr.z, v3 = o.w + xr.w;

    float sum = v0 + v1 + v2 + v3;
    float sq  = v0 * v0 + v1 * v1 + v2 * v2 + v3 * v3;
    #pragma unroll
    for (int d = 16; d; d >>= 1) {
        sum += __shfl_xor_sync(0xFFFFFFFFu, sum, d);
        sq  += __shfl_xor_sync(0xFFFFFFFFu, sq, d);
    }
    const float mu  = sum * (1.f / 128.f);
    const float var = sq * (1.f / 128.f) - mu * mu;
    const float rs  = rsqrtf(var + 1e-5f);

    const float4 g  = *(const float4*)(gamma + lane * 4);
    const float4 bt = *(const float4*)(beta + lane * 4);
    float4 r;
    r.x = (v0 - mu) * rs * g.x + bt.x;
    r.y = (v1 - mu) * rs * g.y + bt.y;
    r.z = (v2 - mu) * rs * g.z + bt.z;
    r.w = (v3 - mu) * rs * g.w + bt.w;
    *(float4*)(out + off) = r;
}

// ---------------------------------------------------------------------------
extern "C" void kernel_launch(void* const* d_in, const int* in_sizes, int n_in,
                              void* d_out, int out_size) {
    const float* x     = (const float*)d_in[0];
    const float* qm    = (const float*)d_in[2];
    const float* km    = (const float*)d_in[3];
    const float* vm    = (const float*)d_in[4];
    const float* pmat  = (const float*)d_in[5];
    const float* gamma = (const float*)d_in[6];
    const float* beta  = (const float*)d_in[7];
    float* out = (float*)d_out;

    const int smem_qkv  = (HH * HH + 32 * HH) * sizeof(float);  // 80KB
    const int smem_attn = SS * HSZ * 2 * sizeof(float);         // 64KB
    const int smem_proj = (HH * HH + 32 * HH) * sizeof(float);  // 80KB

    cudaFuncSetAttribute(qkv_kernel,  cudaFuncAttributeMaxDynamicSharedMemorySize, smem_qkv);
    cudaFuncSetAttribute(attn_kernel, cudaFuncAttributeMaxDynamicSharedMemorySize, smem_attn);
    cudaFuncSetAttribute(proj_kernel, cudaFuncAttributeMaxDynamicSharedMemorySize, smem_proj);

    dim3 g1(JJ, BB, 3);
    qkv_kernel<<<g1, 256, smem_qkv>>>(x, qm, km, vm);

    dim3 g2(JJ, NHEAD, BB);
    attn_kernel<<<g2, 512, smem_attn>>>();

    dim3 g3(JJ, (BB * SS) / 128);
    proj_kernel<<<g3, 256, smem_proj>>>(pmat, out);

    ln_kernel<<<(BB * SS * JJ) / 8, 256>>>(x, gamma, beta, out);
}

// round 3
// speedup vs baseline: 1.5422x; 1.5422x over previous
#include <cuda_runtime.h>
#include <math.h>

#define BB 4
#define SS 512
#define JJ 24
#define HH 128
#define NHEAD 8
#define HSZ 16
#define WS 132   // padded smem stride (banks: (132*r+k)%32 = (4r+k)%32)

// Scratch (device globals — no allocation allowed)
// q/k/v layout: (b, j, s, col) with col = n*16 + d  -> coalesced MMA epilogue
__device__ float g_q[BB*JJ*SS*HH];
__device__ float g_k[BB*JJ*SS*HH];
__device__ float g_v[BB*JJ*SS*HH];
__device__ float g_ao[BB*SS*JJ*HH];   // attention out, (b,s,j,h) h=n*16+d

// ---- tf32 helpers ---------------------------------------------------------
__device__ __forceinline__ unsigned f2tf32(float f) {
    unsigned r; asm("cvt.rna.tf32.f32 %0, %1;" : "=r"(r) : "f"(f)); return r;
}
__device__ __forceinline__ void mma8(float* c, unsigned a0, unsigned a1,
                                     unsigned a2, unsigned a3,
                                     unsigned b0, unsigned b1) {
    asm("mma.sync.aligned.m16n8k8.row.col.f32.tf32.tf32.f32 "
        "{%0,%1,%2,%3},{%4,%5,%6,%7},{%8,%9},{%0,%1,%2,%3};"
        : "+f"(c[0]), "+f"(c[1]), "+f"(c[2]), "+f"(c[3])
        : "r"(a0), "r"(a1), "r"(a2), "r"(a3), "r"(b0), "r"(b1));
}

// ---------------------------------------------------------------------------
// Kernel 1: QKV projection via tensor cores (tf32 mma).
// Per block (j,b,mat): C(512x128) = X(512x128) @ W(128x128), fp32 accum.
// grid (24,4,3), block 256 (8 warps), smem = (128+64)*132*4 = 101376 B
// ---------------------------------------------------------------------------
__global__ void __launch_bounds__(256) qkv_kernel(const float* __restrict__ x,
                           const float* __restrict__ qm,
                           const float* __restrict__ km,
                           const float* __restrict__ vm) {
    const int j = blockIdx.x;
    const int b = blockIdx.y;
    const int m = blockIdx.z;
    const float* W = (m == 0) ? qm : ((m == 1) ? km : vm);
    float* dst = (m == 0) ? g_q : ((m == 1) ? g_k : g_v);

    extern __shared__ unsigned smu[];
    unsigned* sW = smu;             // [col][h] transposed, tf32 bits, stride WS
    unsigned* sX = smu + HH * WS;   // [64 rows][h], tf32 bits, stride WS

    const int tid  = threadIdx.x;
    const int warp = tid >> 5, lane = tid & 31;
    const int gid  = lane >> 2, tig = lane & 3;
    const int wr0  = (warp & 1) * 32;   // warp row tile within 64-row chunk
    const int wc0  = (warp >> 1) * 32;  // warp col tile within 128 cols

    // Load W transposed into sW[col][h] (global contiguous per n-head block)
    for (int idx = tid; idx < HH * HH; idx += 256) {
        const int n8 = idx >> 11, rem = idx & 2047;
        const int h = rem >> 4, d = rem & 15;
        const int col = n8 * HSZ + d;
        sW[col * WS + h] = f2tf32(W[(size_t)(n8 * JJ + j) * 2048 + rem]);
    }

    float* db_all = dst + (size_t)((b * JJ + j) * SS) * HH;

    for (int c0 = 0; c0 < SS; c0 += 64) {
        __syncthreads();
        for (int i = tid; i < 64 * HH; i += 256) {
            const int r = i >> 7, h = i & 127;
            sX[r * WS + h] =
                f2tf32(x[((size_t)(b * SS + c0 + r) * JJ + j) * HH + h]);
        }
        __syncthreads();

        float ccA[4][4], ccB[4][4];
        #pragma unroll
        for (int cf = 0; cf < 4; cf++)
            #pragma unroll
            for (int i = 0; i < 4; i++) { ccA[cf][i] = 0.f; ccB[cf][i] = 0.f; }

        #pragma unroll
        for (int k0 = 0; k0 < HH; k0 += 8) {
            const int rA = (wr0 + gid) * WS + k0 + tig;
            const unsigned aA0 = sX[rA];
            const unsigned aA1 = sX[rA + 8 * WS];
            const unsigned aA2 = sX[rA + 4];
            const unsigned aA3 = sX[rA + 8 * WS + 4];
            const unsigned aB0 = sX[rA + 16 * WS];
            const unsigned aB1 = sX[rA + 24 * WS];
            const unsigned aB2 = sX[rA + 16 * WS + 4];
            const unsigned aB3 = sX[rA + 24 * WS + 4];
            #pragma unroll
            for (int cf = 0; cf < 4; cf++) {
                const int n0 = wc0 + cf * 8;
                const unsigned b0 = sW[(n0 + gid) * WS + k0 + tig];
                const unsigned b1 = sW[(n0 + gid) * WS + k0 + tig + 4];
                mma8(ccA[cf], aA0, aA1, aA2, aA3, b0, b1);
                mma8(ccB[cf], aB0, aB1, aB2, aB3, b0, b1);
            }
        }

        float* db = db_all + (size_t)c0 * HH;
        const int rr = wr0 + gid;
        #pragma unroll
        for (int cf = 0; cf < 4; cf++) {
            const int col = wc0 + cf * 8 + 2 * tig;
            *(float2*)&db[(rr     ) * HH + col] = make_float2(ccA[cf][0], ccA[cf][1]);
            *(float2*)&db[(rr +  8) * HH + col] = make_float2(ccA[cf][2], ccA[cf][3]);
            *(float2*)&db[(rr + 16) * HH + col] = make_float2(ccB[cf][0], ccB[cf][1]);
            *(float2*)&db[(rr + 24) * HH + col] = make_float2(ccB[cf][2], ccB[cf][3]);
        }
    }
}

// ---------------------------------------------------------------------------
// Kernel 2: fused causal attention per (b,n,j). One thread per query s,
// online softmax, K/V tiles in SMEM (scalar fp32 — proven path).
// grid (24, 8, 4), block 512, smem = 512*16*2*4 = 64KB
// ---------------------------------------------------------------------------
__global__ void __launch_bounds__(512, 2) attn_kernel() {
    const int j = blockIdx.x;
    const int n = blockIdx.y;
    const int b = blockIdx.z;

    extern __shared__ float sm2[];
    float* sK = sm2;             // [512][16]
    float* sV = sm2 + SS * HSZ;  // [512][16]

    const int tid = threadIdx.x;  // 512
    const size_t base = (size_t)((b * JJ + j) * SS) * HH;
    const int nc = n * HSZ;

    for (int idx = tid * 4; idx < SS * HSZ; idx += 512 * 4) {
        const int s = idx >> 4, d = idx & 15;
        *(float4*)&sK[idx] = *(const float4*)&g_k[base + (size_t)s * HH + nc + d];
        *(float4*)&sV[idx] = *(const float4*)&g_v[base + (size_t)s * HH + nc + d];
    }
    __syncthreads();

    const int s = tid;
    const float4 q0 = *(const float4*)&g_q[base + (size_t)s * HH + nc + 0];
    const float4 q1 = *(const float4*)&g_q[base + (size_t)s * HH + nc + 4];
    const float4 q2 = *(const float4*)&g_q[base + (size_t)s * HH + nc + 8];
    const float4 q3 = *(const float4*)&g_q[base + (size_t)s * HH + nc + 12];

    float m = -1e30f, l = 0.f;
    float acc[16];
    #pragma unroll
    for (int i = 0; i < 16; i++) acc[i] = 0.f;

    for (int t = 0; t <= s; ++t) {
        const float4 k0 = *(const float4*)&sK[t * HSZ + 0];
        const float4 k1 = *(const float4*)&sK[t * HSZ + 4];
        const float4 k2 = *(const float4*)&sK[t * HSZ + 8];
        const float4 k3 = *(const float4*)&sK[t * HSZ + 12];
        float d0 = q0.x * k0.x + q0.y * k0.y + q0.z * k0.z + q0.w * k0.w;
        float d1 = q1.x * k1.x + q1.y * k1.y + q1.z * k1.z + q1.w * k1.w;
        float d2 = q2.x * k2.x + q2.y * k2.y + q2.z * k2.z + q2.w * k2.w;
        float d3 = q3.x * k3.x + q3.y * k3.y + q3.z * k3.z + q3.w * k3.w;
        const float score = ((d0 + d1) + (d2 + d3)) * 0.25f;  // 1/sqrt(16)

        float p;
        if (score > m) {
            const float corr = __expf(m - score);
            m = score;
            #pragma unroll
            for (int i = 0; i < 16; i++) acc[i] *= corr;
            l = l * corr + 1.f;
            p = 1.f;
        } else {
            p = __expf(score - m);
            l += p;
        }

        const float4 v0 = *(const float4*)&sV[t * HSZ + 0];
        const float4 v1 = *(const float4*)&sV[t * HSZ + 4];
        const float4 v2 = *(const float4*)&sV[t * HSZ + 8];
        const float4 v3 = *(const float4*)&sV[t * HSZ + 12];
        acc[0]  += p * v0.x;  acc[1]  += p * v0.y;  acc[2]  += p * v0.z;  acc[3]  += p * v0.w;
        acc[4]  += p * v1.x;  acc[5]  += p * v1.y;  acc[6]  += p * v1.z;  acc[7]  += p * v1.w;
        acc[8]  += p * v2.x;  acc[9]  += p * v2.y;  acc[10] += p * v2.z;  acc[11] += p * v2.w;
        acc[12] += p * v3.x;  acc[13] += p * v3.y;  acc[14] += p * v3.z;  acc[15] += p * v3.w;
    }

    const float inv = 1.f / l;
    float* o = &g_ao[(size_t)((b * SS + s) * JJ + j) * HH + nc];
    #pragma unroll
    for (int i = 0; i < 4; i++) {
        float4 r;
        r.x = acc[4 * i + 0] * inv;
        r.y = acc[4 * i + 1] * inv;
        r.z = acc[4 * i + 2] * inv;
        r.w = acc[4 * i + 3] * inv;
        *(float4*)&o[4 * i] = r;
    }
}

// ---------------------------------------------------------------------------
// Kernel 3: per-joint output projection via tensor cores (tf32 mma).
// Per block: 128 rows of (b*S+s) for one j; C = AO(128x128) @ P_j(128x128)
// grid (24, 16), block 256, smem = 101376 B
// ---------------------------------------------------------------------------
__global__ void __launch_bounds__(256) proj_kernel(const float* __restrict__ P,
                                                   float* __restrict__ out) {
    const int j  = blockIdx.x;
    const int r0 = blockIdx.y * 128;

    extern __shared__ unsigned smu3[];
    unsigned* sPt = smu3;             // [k_out][h] transposed, stride WS
    unsigned* sA  = smu3 + HH * WS;   // [64 rows][h], stride WS

    const int tid  = threadIdx.x;
    const int warp = tid >> 5, lane = tid & 31;
    const int gid  = lane >> 2, tig = lane & 3;
    const int wr0  = (warp & 1) * 32;
    const int wc0  = (warp >> 1) * 32;

    // P[j][h][k] -> sPt[k][h]
    for (int idx = tid; idx < HH * HH; idx += 256) {
        const int h = idx >> 7, k = idx & 127;
        sPt[k * WS + h] = f2tf32(P[(size_t)j * HH * HH + idx]);
    }

    for (int c0 = 0; c0 < 128; c0 += 64) {
        __syncthreads();
        for (int i = tid; i < 64 * HH; i += 256) {
            const int r = i >> 7, h = i & 127;
            sA[r * WS + h] =
                f2tf32(g_ao[(size_t)((r0 + c0 + r) * JJ + j) * HH + h]);
        }
        __syncthreads();

        float ccA[4][4], ccB[4][4];
        #pragma unroll
        for (int cf = 0; cf < 4; cf++)
            #pragma unroll
            for (int i = 0; i < 4; i++) { ccA[cf][i] = 0.f; ccB[cf][i] = 0.f; }

        #pragma unroll
        for (int k0 = 0; k0 < HH; k0 += 8) {
            const int rA = (wr0 + gid) * WS + k0 + tig;
            const unsigned aA0 = sA[rA];
            const unsigned aA1 = sA[rA + 8 * WS];
            const unsigned aA2 = sA[rA + 4];
            const unsigned aA3 = sA[rA + 8 * WS + 4];
            const unsigned aB0 = sA[rA + 16 * WS];
            const unsigned aB1 = sA[rA + 24 * WS];
            const unsigned aB2 = sA[rA + 16 * WS + 4];
            const unsigned aB3 = sA[rA + 24 * WS + 4];
            #pragma unroll
            for (int cf = 0; cf < 4; cf++) {
                const int n0 = wc0 + cf * 8;
                const unsigned b0 = sPt[(n0 + gid) * WS + k0 + tig];
                const unsigned b1 = sPt[(n0 + gid) * WS + k0 + tig + 4];
                mma8(ccA[cf], aA0, aA1, aA2, aA3, b0, b1);
                mma8(ccB[cf], aB0, aB1, aB2, aB3, b0, b1);
            }
        }

        const int rr = r0 + c0 + wr0 + gid;
        #pragma unroll
        for (int cf = 0; cf < 4; cf++) {
            const int col = wc0 + cf * 8 + 2 * tig;
            *(float2*)&out[(size_t)((rr     ) * JJ + j) * HH + col] = make_float2(ccA[cf][0], ccA[cf][1]);
            *(float2*)&out[(size_t)((rr +  8) * JJ + j) * HH + col] = make_float2(ccA[cf][2], ccA[cf][3]);
            *(float2*)&out[(size_t)((rr + 16) * JJ + j) * HH + col] = make_float2(ccB[cf][0], ccB[cf][1]);
            *(float2*)&out[(size_t)((rr + 24) * JJ + j) * HH + col] = make_float2(ccB[cf][2], ccB[cf][3]);
        }
    }
}

// ---------------------------------------------------------------------------
// Kernel 4: residual + LayerNorm, in place on d_out. One warp per row.
// ---------------------------------------------------------------------------
__global__ void ln_kernel(const float* __restrict__ x,
                          const float* __restrict__ gamma,
                          const float* __restrict__ beta,
                          float* __restrict__ out) {
    const int row  = blockIdx.x * 8 + (threadIdx.x >> 5);
    const int lane = threadIdx.x & 31;
    const size_t off = (size_t)row * HH + lane * 4;

    const float4 o  = *(const float4*)(out + off);
    const float4 xr = *(const float4*)(x + off);
    const float v0 = o.x + xr.x, v1 = o.y + xr.y, v2 = o.z + xr.z, v3 = o.w + xr.w;

    float sum = v0 + v1 + v2 + v3;
    float sq  = v0 * v0 + v1 * v1 + v2 * v2 + v3 * v3;
    #pragma unroll
    for (int d = 16; d; d >>= 1) {
        sum += __shfl_xor_sync(0xFFFFFFFFu, sum, d);
        sq  += __shfl_xor_sync(0xFFFFFFFFu, sq, d);
    }
    const float mu  = sum * (1.f / 128.f);
    const float var = sq * (1.f / 128.f) - mu * mu;
    const float rs  = rsqrtf(var + 1e-5f);

    const float4 g  = *(const float4*)(gamma + lane * 4);
    const float4 bt = *(const float4*)(beta + lane * 4);
    float4 r;
    r.x = (v0 - mu) * rs * g.x + bt.x;
    r.y = (v1 - mu) * rs * g.y + bt.y;
    r.z = (v2 - mu) * rs * g.z + bt.z;
    r.w = (v3 - mu) * rs * g.w + bt.w;
    *(float4*)(out + off) = r;
}

// ---------------------------------------------------------------------------
extern "C" void kernel_launch(void* const* d_in, const int* in_sizes, int n_in,
                              void* d_out, int out_size) {
    const float* x     = (const float*)d_in[0];
    const float* qm    = (const float*)d_in[2];
    const float* km    = (const float*)d_in[3];
    const float* vm    = (const float*)d_in[4];
    const float* pmat  = (const float*)d_in[5];
    const float* gamma = (const float*)d_in[6];
    const float* beta  = (const float*)d_in[7];
    float* out = (float*)d_out;

    const int smem_mma  = (HH + 64) * WS * sizeof(unsigned);  // 101376
    const int smem_attn = SS * HSZ * 2 * sizeof(float);       // 64KB

    cudaFuncSetAttribute(qkv_kernel,  cudaFuncAttributeMaxDynamicSharedMemorySize, smem_mma);
    cudaFuncSetAttribute(attn_kernel, cudaFuncAttributeMaxDynamicSharedMemorySize, smem_attn);
    cudaFuncSetAttribute(proj_kernel, cudaFuncAttributeMaxDynamicSharedMemorySize, smem_mma);

    dim3 g1(JJ, BB, 3);
    qkv_kernel<<<g1, 256, smem_mma>>>(x, qm, km, vm);

    dim3 g2(JJ, NHEAD, BB);
    attn_kernel<<<g2, 512, smem_attn>>>();

    dim3 g3(JJ, (BB * SS) / 128);
    proj_kernel<<<g3, 256, smem_mma>>>(pmat, out);

    ln_kernel<<<(BB * SS * JJ) / 8, 256>>>(x, gamma, beta, out);
}

// round 4
// speedup vs baseline: 2.9577x; 1.9178x over previous
#include <cuda_runtime.h>
#include <math.h>

#define BB 4
#define SS 512
#define JJ 24
#define HH 128
#define NHEAD 8
#define HSZ 16
#define WS 132   // padded smem stride for GEMM kernels

// Scratch (device globals — no allocation allowed)
// q/k/v layout: (b, j, s, col) with col = n*16 + d
__device__ float g_q[BB*JJ*SS*HH];
__device__ float g_k[BB*JJ*SS*HH];
__device__ float g_v[BB*JJ*SS*HH];
__device__ float g_ao[BB*SS*JJ*HH];   // attention out, (b,s,j,h) h=n*16+d

// ---- tf32 helpers ---------------------------------------------------------
__device__ __forceinline__ unsigned f2tf32(float f) {
    unsigned r; asm("cvt.rna.tf32.f32 %0, %1;" : "=r"(r) : "f"(f)); return r;
}
__device__ __forceinline__ void mma8(float* c, unsigned a0, unsigned a1,
                                     unsigned a2, unsigned a3,
                                     unsigned b0, unsigned b1) {
    asm("mma.sync.aligned.m16n8k8.row.col.f32.tf32.tf32.f32 "
        "{%0,%1,%2,%3},{%4,%5,%6,%7},{%8,%9},{%0,%1,%2,%3};"
        : "+f"(c[0]), "+f"(c[1]), "+f"(c[2]), "+f"(c[3])
        : "r"(a0), "r"(a1), "r"(a2), "r"(a3), "r"(b0), "r"(b1));
}

// ---------------------------------------------------------------------------
// Kernel 1: QKV projection via tensor cores (tf32 mma).  (unchanged, proven)
// ---------------------------------------------------------------------------
__global__ void __launch_bounds__(256) qkv_kernel(const float* __restrict__ x,
                           const float* __restrict__ qm,
                           const float* __restrict__ km,
                           const float* __restrict__ vm) {
    const int j = blockIdx.x;
    const int b = blockIdx.y;
    const int m = blockIdx.z;
    const float* W = (m == 0) ? qm : ((m == 1) ? km : vm);
    float* dst = (m == 0) ? g_q : ((m == 1) ? g_k : g_v);

    extern __shared__ unsigned smu[];
    unsigned* sW = smu;             // [col][h] transposed, stride WS
    unsigned* sX = smu + HH * WS;   // [64 rows][h], stride WS

    const int tid  = threadIdx.x;
    const int warp = tid >> 5, lane = tid & 31;
    const int gid  = lane >> 2, tig = lane & 3;
    const int wr0  = (warp & 1) * 32;
    const int wc0  = (warp >> 1) * 32;

    for (int idx = tid; idx < HH * HH; idx += 256) {
        const int n8 = idx >> 11, rem = idx & 2047;
        const int d = rem & 15;
        const int col = n8 * HSZ + d;
        const int h = rem >> 4;
        sW[col * WS + h] = f2tf32(W[(size_t)(n8 * JJ + j) * 2048 + rem]);
    }

    float* db_all = dst + (size_t)((b * JJ + j) * SS) * HH;

    for (int c0 = 0; c0 < SS; c0 += 64) {
        __syncthreads();
        for (int i = tid; i < 64 * HH; i += 256) {
            const int r = i >> 7, h = i & 127;
            sX[r * WS + h] =
                f2tf32(x[((size_t)(b * SS + c0 + r) * JJ + j) * HH + h]);
        }
        __syncthreads();

        float ccA[4][4], ccB[4][4];
        #pragma unroll
        for (int cf = 0; cf < 4; cf++)
            #pragma unroll
            for (int i = 0; i < 4; i++) { ccA[cf][i] = 0.f; ccB[cf][i] = 0.f; }

        #pragma unroll
        for (int k0 = 0; k0 < HH; k0 += 8) {
            const int rA = (wr0 + gid) * WS + k0 + tig;
            const unsigned aA0 = sX[rA];
            const unsigned aA1 = sX[rA + 8 * WS];
            const unsigned aA2 = sX[rA + 4];
            const unsigned aA3 = sX[rA + 8 * WS + 4];
            const unsigned aB0 = sX[rA + 16 * WS];
            const unsigned aB1 = sX[rA + 24 * WS];
            const unsigned aB2 = sX[rA + 16 * WS + 4];
            const unsigned aB3 = sX[rA + 24 * WS + 4];
            #pragma unroll
            for (int cf = 0; cf < 4; cf++) {
                const int n0 = wc0 + cf * 8;
                const unsigned b0 = sW[(n0 + gid) * WS + k0 + tig];
                const unsigned b1 = sW[(n0 + gid) * WS + k0 + tig + 4];
                mma8(ccA[cf], aA0, aA1, aA2, aA3, b0, b1);
                mma8(ccB[cf], aB0, aB1, aB2, aB3, b0, b1);
            }
        }

        float* db = db_all + (size_t)c0 * HH;
        const int rr = wr0 + gid;
        #pragma unroll
        for (int cf = 0; cf < 4; cf++) {
            const int col = wc0 + cf * 8 + 2 * tig;
            *(float2*)&db[(rr     ) * HH + col] = make_float2(ccA[cf][0], ccA[cf][1]);
            *(float2*)&db[(rr +  8) * HH + col] = make_float2(ccA[cf][2], ccA[cf][3]);
            *(float2*)&db[(rr + 16) * HH + col] = make_float2(ccB[cf][0], ccB[cf][1]);
            *(float2*)&db[(rr + 24) * HH + col] = make_float2(ccB[cf][2], ccB[cf][3]);
        }
    }
}

// ---------------------------------------------------------------------------
// Kernel 2: flash attention per (b,n,j) with tf32 tensor-core MMAs.
// Block 512 threads (16 warps). Warp w owns m-tiles {w, 31-w} (16 rows each).
// Full K/V/Q staged in SMEM as tf32; P routed through per-warp SMEM.
// smem = (512*20 + 512*24 + 512*20) * 4 = 128 KB
// ---------------------------------------------------------------------------
__global__ void __launch_bounds__(512) attn_kernel() {
    const int j = blockIdx.x;
    const int n = blockIdx.y;
    const int b = blockIdx.z;

    extern __shared__ unsigned smA[];
    unsigned* sK = smA;                         // [512][20]
    unsigned* sV = smA + 512 * 20;              // [512][24]
    unsigned* sQ = smA + 512 * 20 + 512 * 24;   // [512][20]; later P region

    const int tid  = threadIdx.x;
    const int warp = tid >> 5, lane = tid & 31;
    const int gid  = lane >> 2, tig = lane & 3;
    const size_t base = (size_t)((b * JJ + j) * SS) * HH + n * HSZ;

    // ---- stage Q (pre-scaled by 1/sqrt(16)), K, V as tf32 ----
    {
        const int r = tid;  // one row per thread
        const float* gq = &g_q[base + (size_t)r * HH];
        const float* gk = &g_k[base + (size_t)r * HH];
        const float* gv = &g_v[base + (size_t)r * HH];
        #pragma unroll
        for (int d4 = 0; d4 < 4; d4++) {
            const float4 q = *(const float4*)(gq + 4 * d4);
            const float4 k = *(const float4*)(gk + 4 * d4);
            const float4 v = *(const float4*)(gv + 4 * d4);
            *(uint4*)&sQ[r * 20 + 4 * d4] = make_uint4(
                f2tf32(q.x * 0.25f), f2tf32(q.y * 0.25f),
                f2tf32(q.z * 0.25f), f2tf32(q.w * 0.25f));
            *(uint4*)&sK[r * 20 + 4 * d4] = make_uint4(
                f2tf32(k.x), f2tf32(k.y), f2tf32(k.z), f2tf32(k.w));
            *(uint4*)&sV[r * 24 + 4 * d4] = make_uint4(
                f2tf32(v.x), f2tf32(v.y), f2tf32(v.z), f2tf32(v.w));
        }
    }
    __syncthreads();

    // ---- load Q fragments for both owned m-tiles ----
    unsigned qf[2][8];
    #pragma unroll
    for (int t = 0; t < 2; t++) {
        const int mt = t ? (31 - warp) : warp;
        const int r0 = mt * 16;
        #pragma unroll
        for (int kf = 0; kf < 2; kf++) {
            qf[t][kf * 4 + 0] = sQ[(r0 + gid) * 20 + kf * 8 + tig];
            qf[t][kf * 4 + 1] = sQ[(r0 + gid + 8) * 20 + kf * 8 + tig];
            qf[t][kf * 4 + 2] = sQ[(r0 + gid) * 20 + kf * 8 + tig + 4];
            qf[t][kf * 4 + 3] = sQ[(r0 + gid + 8) * 20 + kf * 8 + tig + 4];
        }
    }
    __syncthreads();  // sQ now reusable as P region

    unsigned* Pw = sQ + warp * 576;  // per-warp P: [16][36]

    #pragma unroll
    for (int t = 0; t < 2; t++) {
        const int mt = t ? (31 - warp) : warp;
        const int r0 = mt * 16;
        const int ktmax = (r0 + 15) >> 5;

        float m0 = -1e30f, m1 = -1e30f, l0 = 0.f, l1 = 0.f;
        float oc[2][4];
        #pragma unroll
        for (int on = 0; on < 2; on++)
            #pragma unroll
            for (int i = 0; i < 4; i++) oc[on][i] = 0.f;

        for (int kt = 0; kt <= ktmax; kt++) {
            const int k0 = kt * 32;

            // ---- scores = Q @ K^T (8 MMAs) ----
            float sc[4][4];
            #pragma unroll
            for (int nt = 0; nt < 4; nt++)
                #pragma unroll
                for (int i = 0; i < 4; i++) sc[nt][i] = 0.f;

            #pragma unroll
            for (int nt = 0; nt < 4; nt++) {
                #pragma unroll
                for (int kf = 0; kf < 2; kf++) {
                    const unsigned b0 = sK[(k0 + nt * 8 + gid) * 20 + kf * 8 + tig];
                    const unsigned b1 = sK[(k0 + nt * 8 + gid) * 20 + kf * 8 + tig + 4];
                    mma8(sc[nt], qf[t][kf * 4], qf[t][kf * 4 + 1],
                         qf[t][kf * 4 + 2], qf[t][kf * 4 + 3], b0, b1);
                }
            }

            // ---- causal mask on the diagonal tile only ----
            if (kt == ktmax) {
                const int ra = r0 + gid, rb = ra + 8;
                #pragma unroll
                for (int nt = 0; nt < 4; nt++) {
                    const int key = k0 + nt * 8 + 2 * tig;
                    if (key     > ra) sc[nt][0] = -1e30f;
                    if (key + 1 > ra) sc[nt][1] = -1e30f;
                    if (key     > rb) sc[nt][2] = -1e30f;
                    if (key + 1 > rb) sc[nt][3] = -1e30f;
                }
            }

            // ---- online softmax (rows gid -> c0,c1 ; gid+8 -> c2,c3) ----
            float mx0 = fmaxf(fmaxf(sc[0][0], sc[0][1]), fmaxf(sc[1][0], sc[1][1]));
            mx0 = fmaxf(mx0, fmaxf(fmaxf(sc[2][0], sc[2][1]), fmaxf(sc[3][0], sc[3][1])));
            float mx1 = fmaxf(fmaxf(sc[0][2], sc[0][3]), fmaxf(sc[1][2], sc[1][3]));
            mx1 = fmaxf(mx1, fmaxf(fmaxf(sc[2][2], sc[2][3]), fmaxf(sc[3][2], sc[3][3])));
            mx0 = fmaxf(mx0, __shfl_xor_sync(0xFFFFFFFFu, mx0, 1));
            mx0 = fmaxf(mx0, __shfl_xor_sync(0xFFFFFFFFu, mx0, 2));
            mx1 = fmaxf(mx1, __shfl_xor_sync(0xFFFFFFFFu, mx1, 1));
            mx1 = fmaxf(mx1, __shfl_xor_sync(0xFFFFFFFFu, mx1, 2));

            const float mn0 = fmaxf(m0, mx0), mn1 = fmaxf(m1, mx1);
            const float c0 = __expf(m0 - mn0), c1 = __expf(m1 - mn1);
            m0 = mn0; m1 = mn1;
            l0 *= c0;  l1 *= c1;
            #pragma unroll
            for (int on = 0; on < 2; on++) {
                oc[on][0] *= c0; oc[on][1] *= c0;
                oc[on][2] *= c1; oc[on][3] *= c1;
            }

            #pragma unroll
            for (int nt = 0; nt < 4; nt++) {
                const float p0 = __expf(sc[nt][0] - m0);
                const float p1 = __expf(sc[nt][1] - m0);
                const float p2 = __expf(sc[nt][2] - m1);
                const float p3 = __expf(sc[nt][3] - m1);
                l0 += p0 + p1;  l1 += p2 + p3;
                *(uint2*)&Pw[gid * 36 + nt * 8 + 2 * tig] =
                    make_uint2(f2tf32(p0), f2tf32(p1));
                *(uint2*)&Pw[(gid + 8) * 36 + nt * 8 + 2 * tig] =
                    make_uint2(f2tf32(p2), f2tf32(p3));
            }
            __syncwarp();

            // ---- O += P @ V (8 MMAs) ----
            #pragma unroll
            for (int kf = 0; kf < 4; kf++) {
                const unsigned a0 = Pw[gid * 36 + kf * 8 + tig];
                const unsigned a1 = Pw[(gid + 8) * 36 + kf * 8 + tig];
                const unsigned a2 = Pw[gid * 36 + kf * 8 + tig + 4];
                const unsigned a3 = Pw[(gid + 8) * 36 + kf * 8 + tig + 4];
                #pragma unroll
                for (int on = 0; on < 2; on++) {
                    const unsigned b0 = sV[(k0 + kf * 8 + tig) * 24 + on * 8 + gid];
                    const unsigned b1 = sV[(k0 + kf * 8 + tig + 4) * 24 + on * 8 + gid];
                    mma8(oc[on], a0, a1, a2, a3, b0, b1);
                }
            }
            __syncwarp();
        }

        // ---- epilogue: normalize and store ----
        l0 += __shfl_xor_sync(0xFFFFFFFFu, l0, 1);
        l0 += __shfl_xor_sync(0xFFFFFFFFu, l0, 2);
        l1 += __shfl_xor_sync(0xFFFFFFFFu, l1, 1);
        l1 += __shfl_xor_sync(0xFFFFFFFFu, l1, 2);
        const float i0 = 1.f / l0, i1 = 1.f / l1;
        const int ra = r0 + gid, rb = ra + 8;
        #pragma unroll
        for (int on = 0; on < 2; on++) {
            const int col = n * HSZ + on * 8 + 2 * tig;
            *(float2*)&g_ao[((size_t)(b * SS + ra) * JJ + j) * HH + col] =
                make_float2(oc[on][0] * i0, oc[on][1] * i0);
            *(float2*)&g_ao[((size_t)(b * SS + rb) * JJ + j) * HH + col] =
                make_float2(oc[on][2] * i1, oc[on][3] * i1);
        }
    }
}

// ---------------------------------------------------------------------------
// Kernel 3: per-joint output projection via tensor cores (unchanged, proven)
// ---------------------------------------------------------------------------
__global__ void __launch_bounds__(256) proj_kernel(const float* __restrict__ P,
                                                   float* __restrict__ out) {
    const int j  = blockIdx.x;
    const int r0 = blockIdx.y * 128;

    extern __shared__ unsigned smu3[];
    unsigned* sPt = smu3;             // [k_out][h], stride WS
    unsigned* sA  = smu3 + HH * WS;   // [64 rows][h], stride WS

    const int tid  = threadIdx.x;
    const int warp = tid >> 5, lane = tid & 31;
    const int gid  = lane >> 2, tig = lane & 3;
    const int wr0  = (warp & 1) * 32;
    const int wc0  = (warp >> 1) * 32;

    for (int idx = tid; idx < HH * HH; idx += 256) {
        const int h = idx >> 7, k = idx & 127;
        sPt[k * WS + h] = f2tf32(P[(size_t)j * HH * HH + idx]);
    }

    for (int c0 = 0; c0 < 128; c0 += 64) {
        __syncthreads();
        for (int i = tid; i < 64 * HH; i += 256) {
            const int r = i >> 7, h = i & 127;
            sA[r * WS + h] =
                f2tf32(g_ao[(size_t)((r0 + c0 + r) * JJ + j) * HH + h]);
        }
        __syncthreads();

        float ccA[4][4], ccB[4][4];
        #pragma unroll
        for (int cf = 0; cf < 4; cf++)
            #pragma unroll
            for (int i = 0; i < 4; i++) { ccA[cf][i] = 0.f; ccB[cf][i] = 0.f; }

        #pragma unroll
        for (int k0 = 0; k0 < HH; k0 += 8) {
            const int rA = (wr0 + gid) * WS + k0 + tig;
            const unsigned aA0 = sA[rA];
            const unsigned aA1 = sA[rA + 8 * WS];
            const unsigned aA2 = sA[rA + 4];
            const unsigned aA3 = sA[rA + 8 * WS + 4];
            const unsigned aB0 = sA[rA + 16 * WS];
            const unsigned aB1 = sA[rA + 24 * WS];
            const unsigned aB2 = sA[rA + 16 * WS + 4];
            const unsigned aB3 = sA[rA + 24 * WS + 4];
            #pragma unroll
            for (int cf = 0; cf < 4; cf++) {
                const int n0 = wc0 + cf * 8;
                const unsigned b0 = sPt[(n0 + gid) * WS + k0 + tig];
                const unsigned b1 = sPt[(n0 + gid) * WS + k0 + tig + 4];
                mma8(ccA[cf], aA0, aA1, aA2, aA3, b0, b1);
                mma8(ccB[cf], aB0, aB1, aB2, aB3, b0, b1);
            }
        }

        const int rr = r0 + c0 + wr0 + gid;
        #pragma unroll
        for (int cf = 0; cf < 4; cf++) {
            const int col = wc0 + cf * 8 + 2 * tig;
            *(float2*)&out[(size_t)((rr     ) * JJ + j) * HH + col] = make_float2(ccA[cf][0], ccA[cf][1]);
            *(float2*)&out[(size_t)((rr +  8) * JJ + j) * HH + col] = make_float2(ccA[cf][2], ccA[cf][3]);
            *(float2*)&out[(size_t)((rr + 16) * JJ + j) * HH + col] = make_float2(ccB[cf][0], ccB[cf][1]);
            *(float2*)&out[(size_t)((rr + 24) * JJ + j) * HH + col] = make_float2(ccB[cf][2], ccB[cf][3]);
        }
    }
}

// ---------------------------------------------------------------------------
// Kernel 4: residual + LayerNorm (unchanged)
// ---------------------------------------------------------------------------
__global__ void ln_kernel(const float* __restrict__ x,
                          const float* __restrict__ gamma,
                          const float* __restrict__ beta,
                          float* __restrict__ out) {
    const int row  = blockIdx.x * 8 + (threadIdx.x >> 5);
    const int lane = threadIdx.x & 31;
    const size_t off = (size_t)row * HH + lane * 4;

    const float4 o  = *(const float4*)(out + off);
    const float4 xr = *(const float4*)(x + off);
    const float v0 = o.x + xr.x, v1 = o.y + xr.y, v2 = o.z + xr.z, v3 = o.w + xr.w;

    float sum = v0 + v1 + v2 + v3;
    float sq  = v0 * v0 + v1 * v1 + v2 * v2 + v3 * v3;
    #pragma unroll
    for (int d = 16; d; d >>= 1) {
        sum += __shfl_xor_sync(0xFFFFFFFFu, sum, d);
        sq  += __shfl_xor_sync(0xFFFFFFFFu, sq, d);
    }
    const float mu  = sum * (1.f / 128.f);
    const float var = sq * (1.f / 128.f) - mu * mu;
    const float rs  = rsqrtf(var + 1e-5f);

    const float4 g  = *(const float4*)(gamma + lane * 4);
    const float4 bt = *(const float4*)(beta + lane * 4);
    float4 r;
    r.x = (v0 - mu) * rs * g.x + bt.x;
    r.y = (v1 - mu) * rs * g.y + bt.y;
    r.z = (v2 - mu) * rs * g.z + bt.z;
    r.w = (v3 - mu) * rs * g.w + bt.w;
    *(float4*)(out + off) = r;
}

// ---------------------------------------------------------------------------
extern "C" void kernel_launch(void* const* d_in, const int* in_sizes, int n_in,
                              void* d_out, int out_size) {
    const float* x     = (const float*)d_in[0];
    const float* qm    = (const float*)d_in[2];
    const float* km    = (const float*)d_in[3];
    const float* vm    = (const float*)d_in[4];
    const float* pmat  = (const float*)d_in[5];
    const float* gamma = (const float*)d_in[6];
    const float* beta  = (const float*)d_in[7];
    float* out = (float*)d_out;

    const int smem_mma  = (HH + 64) * WS * sizeof(unsigned);          // 101376
    const int smem_attn = (512 * 20 + 512 * 24 + 512 * 20) * 4;       // 131072

    cudaFuncSetAttribute(qkv_kernel,  cudaFuncAttributeMaxDynamicSharedMemorySize, smem_mma);
    cudaFuncSetAttribute(attn_kernel, cudaFuncAttributeMaxDynamicSharedMemorySize, smem_attn);
    cudaFuncSetAttribute(proj_kernel, cudaFuncAttributeMaxDynamicSharedMemorySize, smem_mma);

    dim3 g1(JJ, BB, 3);
    qkv_kernel<<<g1, 256, smem_mma>>>(x, qm, km, vm);

    dim3 g2(JJ, NHEAD, BB);
    attn_kernel<<<g2, 512, smem_attn>>>();

    dim3 g3(JJ, (BB * SS) / 128);
    proj_kernel<<<g3, 256, smem_mma>>>(pmat, out);

    ln_kernel<<<(BB * SS * JJ) / 8, 256>>>(x, gamma, beta, out);
}